// round 12
// baseline (speedup 1.0000x reference)
#include <cuda_runtime.h>

#define BATCH    512
#define NROWS    32
#define CDIM     1024
#define RPITCH   1032
#define NTHREADS 512
#define FULLM    0xffffffffu

// staggered row base (floats): rows 4 apart differ by 16B mod 128B -> conflict-free Gram
static __device__ __forceinline__ int rbase(int r) { return r * RPITCH + ((r >> 2) << 2); }

#define XS_FLOATS   (32 * RPITCH + 32 + RPITCH)   /* 33 rows: rbase(32)+RPITCH */
#define D2P_FLOATS  (32 * 33)
#define GTMP_FLOATS (8 * 1056)
#define SQP_FLOATS  34
#define FRED_FLOATS 16
#define SMEM_FLOATS (XS_FLOATS + D2P_FLOATS + GTMP_FLOATS + SQP_FLOATS + FRED_FLOATS)
#define SMEM_BYTES  (SMEM_FLOATS * 4 + 32)

static __device__ __forceinline__ unsigned long long u64min(unsigned long long a, unsigned long long b) {
    return a < b ? a : b;
}

__global__ __launch_bounds__(NTHREADS, 1)
void agg_kernel(const float* __restrict__ x,
                const float* __restrict__ cw,
                const float* __restrict__ cb,
                float* __restrict__ out)
{
    extern __shared__ float smf[];
    float* xs    = smf;
    float* d2p   = smf + XS_FLOATS;
    float* gtmp  = d2p + D2P_FLOATS;
    float* sqp   = gtmp + GTMP_FLOATS;
    float* fredS = sqp + SQP_FLOATS;

    const int tid  = threadIdx.x;
    const int w    = tid >> 5;
    const int lane = tid & 31;
    const int b    = blockIdx.x;

    const float w00 = cw[0], w01 = cw[1], w02 = cw[2];
    const float w10 = cw[3], w11 = cw[4], w12 = cw[5];
    const float bc  = cb[0];

    // ---- load batch rows into staggered smem ----
    {
        const float4* src = (const float4*)(x + (size_t)b * NROWS * CDIM);
        #pragma unroll
        for (int k = 0; k < (NROWS*CDIM/4)/NTHREADS; k++) {
            int e4 = tid + k * NTHREADS;
            float4 v = src[e4];
            int e = e4 * 4;
            int r = e >> 10, c = e & (CDIM - 1);
            *(float4*)(xs + rbase(r) + c) = v;
        }
    }
    __syncthreads();

    // ---- squared norms: 32 rows x 16 lanes ----
    {
        int r = tid >> 4, l16 = tid & 15;
        const float4* row = (const float4*)(xs + rbase(r));
        float s = 0.f;
        #pragma unroll
        for (int k = 0; k < 16; k++) {
            float4 v = row[l16 + 16 * k];
            s += v.x * v.x + v.y * v.y + v.z * v.z + v.w * v.w;
        }
        #pragma unroll
        for (int o = 8; o; o >>= 1) s += __shfl_down_sync(FULLM, s, o, 16);
        if (l16 == 0) sqp[r] = s;
    }

    // ---- 32x32 Gram: 8 c-slices x (8x8 threads, 4x4 tiles), conflict-free ----
    {
        int tslice = tid >> 6;
        int t64 = tid & 63;
        int ty = t64 >> 3, tx = t64 & 7;
        const float4* rA0 = (const float4*)(xs + rbase(4 * ty + 0));
        const float4* rA1 = (const float4*)(xs + rbase(4 * ty + 1));
        const float4* rA2 = (const float4*)(xs + rbase(4 * ty + 2));
        const float4* rA3 = (const float4*)(xs + rbase(4 * ty + 3));
        const float4* rB0 = (const float4*)(xs + rbase(4 * tx + 0));
        const float4* rB1 = (const float4*)(xs + rbase(4 * tx + 1));
        const float4* rB2 = (const float4*)(xs + rbase(4 * tx + 2));
        const float4* rB3 = (const float4*)(xs + rbase(4 * tx + 3));
        float acc[4][4];
        #pragma unroll
        for (int i = 0; i < 4; i++)
            #pragma unroll
            for (int j = 0; j < 4; j++) acc[i][j] = 0.f;

        int c4beg = tslice * 32;
        #pragma unroll 2
        for (int c4 = c4beg; c4 < c4beg + 32; c4++) {
            float4 a0 = rA0[c4], a1 = rA1[c4], a2 = rA2[c4], a3 = rA3[c4];
            float4 b0 = rB0[c4], b1 = rB1[c4], b2 = rB2[c4], b3 = rB3[c4];
            #define GRAM_STEP(C) { \
                float A0=a0.C, A1=a1.C, A2=a2.C, A3=a3.C; \
                float B0=b0.C, B1=b1.C, B2=b2.C, B3=b3.C; \
                acc[0][0]+=A0*B0; acc[0][1]+=A0*B1; acc[0][2]+=A0*B2; acc[0][3]+=A0*B3; \
                acc[1][0]+=A1*B0; acc[1][1]+=A1*B1; acc[1][2]+=A1*B2; acc[1][3]+=A1*B3; \
                acc[2][0]+=A2*B0; acc[2][1]+=A2*B1; acc[2][2]+=A2*B2; acc[2][3]+=A2*B3; \
                acc[3][0]+=A3*B0; acc[3][1]+=A3*B1; acc[3][2]+=A3*B2; acc[3][3]+=A3*B3; }
            GRAM_STEP(x) GRAM_STEP(y) GRAM_STEP(z) GRAM_STEP(w)
            #undef GRAM_STEP
        }
        float* gs = gtmp + tslice * 1056;
        #pragma unroll
        for (int i = 0; i < 4; i++)
            #pragma unroll
            for (int j = 0; j < 4; j++)
                gs[(4 * ty + i) * 33 + (4 * tx + j)] = acc[i][j];
    }
    __syncthreads();
    // deterministic 8-way reduce + finalize
    for (int e = tid; e < 1024; e += NTHREADS) {
        int i = e >> 5, j = e & 31;
        int o = i * 33 + j;
        float d = gtmp[o];
        #pragma unroll
        for (int s = 1; s < 8; s++) d += gtmp[s * 1056 + o];
        d2p[o] = sqp[i] + sqp[j] - 2.f * d;
    }
    __syncthreads();

    // register-replicated logical->physical slot table: lane l holds L[l] (slots 0..32)
    int myL = lane;

    // ---- merge steps ----
    for (int n = NROWS; n >= 2; n--) {
        int a, bb;
        if (n > 2) {
            // (A) barrier-free argmin: EVERY warp scans the full n x n matrix.
            // lane = column j; loop over rows i; 2-partial min chains.
            int Lj = myL;
            unsigned long long kA = ~0ull, kB = ~0ull;
            bool laneOK = (lane < n);
            for (int i = 0; i < n; i += 2) {
                int Li0 = __shfl_sync(FULLM, myL, i);
                int Li1 = __shfl_sync(FULLM, myL, (i + 1) & 31);
                if (laneOK && i != lane) {
                    float v = fmaxf(d2p[Li0 * 33 + Lj], 0.f);
                    kA = u64min(kA, (((unsigned long long)__float_as_uint(v)) << 32) | (unsigned)((i << 8) | lane));
                }
                if (laneOK && (i + 1) < n && (i + 1) != lane) {
                    float v = fmaxf(d2p[Li1 * 33 + Lj], 0.f);
                    kB = u64min(kB, (((unsigned long long)__float_as_uint(v)) << 32) | (unsigned)(((i + 1) << 8) | lane));
                }
            }
            unsigned long long key = u64min(kA, kB);
            #pragma unroll
            for (int o = 16; o; o >>= 1)
                key = u64min(key, __shfl_xor_sync(FULLM, key, o));
            a  = (int)((key >> 8) & 0xff);
            bb = (int)(key & 0xff);
        } else {
            a = 0; bb = 1;
        }

        // (B) perm update in registers, redundantly identical across warps
        int pa, pb, sm = 0;
        {
            int oldL = myL;
            int la0 = __shfl_sync(FULLM, oldL, 0);
            int la1 = __shfl_sync(FULLM, oldL, 1);
            pa = (a == 0) ? la0 : ((a == 1) ? la1 : __shfl_sync(FULLM, oldL, a));
            pb = (bb == 1) ? la1 : __shfl_sync(FULLM, oldL, bb);
            if (n > 2) {
                int p = lane + 1;
                int v = (p == bb) ? 1 : ((a >= 2 && p == a) ? 0 : p);
                int slv = __shfl_sync(FULLM, oldL, v & 31);
                bool actL = (lane >= 1 && lane <= n - 2);
                // free-slot selection over 33 slots, excluding survivors AND pa, pb
                unsigned bit = (actL && slv < 32) ? (1u << slv) : 0u;
                unsigned mask = __reduce_or_sync(FULLM, bit);
                unsigned excl = mask;
                if (pa < 32) excl |= (1u << pa);
                if (pb < 32) excl |= (1u << pb);
                unsigned freeb = ~excl;
                sm = freeb ? (__ffs(freeb) - 1) : 32;
                if (lane == 0) myL = sm;
                else if (actL) myL = slv;
            }
        }

        // (C) conv1d k=3 SAME over rows pa,pb + bias + relu; float2 + shuffles.
        // Merged row goes to slot sm which is disjoint from pa/pb and all
        // survivors -> no read/write hazard, NO barrier needed before the write.
        const float* ra = xs + rbase(pa);
        const float* rb = xs + rbase(pb);
        const int c0 = 2 * tid;
        float2 Av = ((const float2*)ra)[tid];
        float2 Bv = ((const float2*)rb)[tid];
        float am1 = __shfl_up_sync(FULLM, Av.y, 1);
        float bm1 = __shfl_up_sync(FULLM, Bv.y, 1);
        float a2  = __shfl_down_sync(FULLM, Av.x, 1);
        float bv2 = __shfl_down_sync(FULLM, Bv.x, 1);
        if (lane == 0)  { am1 = (tid == 0) ? 0.f : ra[c0 - 1];
                          bm1 = (tid == 0) ? 0.f : rb[c0 - 1]; }
        if (lane == 31) { a2  = (tid == NTHREADS - 1) ? 0.f : ra[c0 + 2];
                          bv2 = (tid == NTHREADS - 1) ? 0.f : rb[c0 + 2]; }
        float m0 = bc + w00 * am1  + w01 * Av.x + w02 * Av.y + w10 * bm1  + w11 * Bv.x + w12 * Bv.y;
        float m1 = bc + w00 * Av.x + w01 * Av.y + w02 * a2   + w10 * Bv.x + w11 * Bv.y + w12 * bv2;
        m0 = fmaxf(m0, 0.f); m1 = fmaxf(m1, 0.f);

        if (n == 2) {
            float* ob = out + (size_t)b * CDIM;
            ((float2*)ob)[tid] = make_float2(m0, m1);
            break;
        }

        float* rm = xs + rbase(sm);
        ((float2*)rm)[tid] = make_float2(m0, m1);
        float sq = m0 * m0 + m1 * m1;
        #pragma unroll
        for (int o = 16; o; o >>= 1) sq += __shfl_down_sync(FULLM, sq, o);
        if (lane == 0) fredS[w] = sq;
        __syncthreads();                       // BAR-D: rm + fred visible

        // (D) sqm from fred (all warps); tid0 persists sqp[sm]
        float sqm;
        {
            float v = fredS[lane & 15];
            #pragma unroll
            for (int o = 8; o; o >>= 1) v += __shfl_xor_sync(FULLM, v, o);
            sqm = v;
        }
        if (tid == 0) sqp[sm] = sqm;

        // (E) distance updates: warp w handles logical targets w+1 and w+17
        {
            int l1 = w + 1, l2 = w + 17;
            bool v1 = (l1 <= n - 2);
            bool v2 = (l2 <= n - 2);
            int t1 = __shfl_sync(FULLM, myL, l1 & 31);
            int t2 = __shfl_sync(FULLM, myL, l2 & 31);
            const float4* rm4 = (const float4*)rm;
            float4 rmv[8];
            float s1 = 0.f, s2 = 0.f;
            if (v1 || v2) {
                #pragma unroll
                for (int k = 0; k < 8; k++) rmv[k] = rm4[lane + 32 * k];
            }
            if (v1) {
                const float4* rt = (const float4*)(xs + rbase(t1));
                #pragma unroll
                for (int k = 0; k < 8; k++) {
                    float4 v = rt[lane + 32 * k];
                    s1 += rmv[k].x * v.x + rmv[k].y * v.y + rmv[k].z * v.z + rmv[k].w * v.w;
                }
            }
            if (v2) {
                const float4* rt = (const float4*)(xs + rbase(t2));
                #pragma unroll
                for (int k = 0; k < 8; k++) {
                    float4 v = rt[lane + 32 * k];
                    s2 += rmv[k].x * v.x + rmv[k].y * v.y + rmv[k].z * v.z + rmv[k].w * v.w;
                }
            }
            #pragma unroll
            for (int o = 16; o; o >>= 1) {
                s1 += __shfl_xor_sync(FULLM, s1, o);
                s2 += __shfl_xor_sync(FULLM, s2, o);
            }
            if (lane == 0) {
                if (v1) {
                    float d2 = sqm + sqp[t1] - 2.f * s1;
                    d2p[sm * 33 + t1] = d2;
                    d2p[t1 * 33 + sm] = d2;
                }
                if (v2) {
                    float d2 = sqm + sqp[t2] - 2.f * s2;
                    d2p[sm * 33 + t2] = d2;
                    d2p[t2 * 33 + sm] = d2;
                }
            }
        }
        __syncthreads();                       // BAR-E: d2p ready for next argmin
    }
}

extern "C" void kernel_launch(void* const* d_in, const int* in_sizes, int n_in,
                              void* d_out, int out_size)
{
    const float* x  = (const float*)d_in[0];
    const float* cw = (const float*)d_in[1];
    const float* cb = (const float*)d_in[2];
    float* out = (float*)d_out;
    cudaFuncSetAttribute(agg_kernel, cudaFuncAttributeMaxDynamicSharedMemorySize, SMEM_BYTES);
    agg_kernel<<<BATCH, NTHREADS, SMEM_BYTES>>>(x, cw, cb, out);
}

// round 14
// speedup vs baseline: 1.6350x; 1.6350x over previous
#include <cuda_runtime.h>

#define BATCH    512
#define NROWS    32
#define CDIM     1024
#define RPITCH   1032
#define NTHREADS 512
#define FULLM    0xffffffffu

// staggered row base (floats): rows 4 apart differ by 16B mod 128B -> conflict-free Gram
static __device__ __forceinline__ int rbase(int r) { return r * RPITCH + ((r >> 2) << 2); }

#define XS_FLOATS   (32 * RPITCH + 32 + RPITCH)   /* 33 rows; = 34088, even */
#define D2P_FLOATS  1090                          /* 33*33 = 1089, padded EVEN for 8B alignment below */
#define GTMP_FLOATS (8 * 1056)
#define SQP_FLOATS  34
#define FRED_FLOATS 16
#define SMEM_FLOATS (XS_FLOATS + D2P_FLOATS + GTMP_FLOATS + SQP_FLOATS + FRED_FLOATS)
#define SMEM_BYTES  (SMEM_FLOATS * 4 + 16 * 8 + 32)

static __device__ __forceinline__ unsigned long long u64min(unsigned long long a, unsigned long long b) {
    return a < b ? a : b;
}

__global__ __launch_bounds__(NTHREADS, 1)
void agg_kernel(const float* __restrict__ x,
                const float* __restrict__ cw,
                const float* __restrict__ cb,
                float* __restrict__ out)
{
    extern __shared__ float smf[];
    float* xs    = smf;
    float* d2p   = smf + XS_FLOATS;
    float* gtmp  = d2p + D2P_FLOATS;
    float* sqp   = gtmp + GTMP_FLOATS;
    float* fredS = sqp + SQP_FLOATS;
    unsigned long long* redS = (unsigned long long*)(fredS + FRED_FLOATS);   // 8B-aligned by construction

    const int tid  = threadIdx.x;
    const int w    = tid >> 5;
    const int lane = tid & 31;
    const int b    = blockIdx.x;

    const float w00 = cw[0], w01 = cw[1], w02 = cw[2];
    const float w10 = cw[3], w11 = cw[4], w12 = cw[5];
    const float bc  = cb[0];

    // static upper-triangle pair for this thread: tid -> (ti, tj), ti < tj < 32
    int ti = 0, tj = 0;
    {
        int k = tid, cnt = 31;
        if (tid < 496) {
            while (k >= cnt) { k -= cnt; ti++; cnt--; }
            tj = ti + 1 + k;
        } else { ti = 0; tj = 32; }   // tj=32 -> never passes tj < n
    }

    // ---- load batch rows into staggered smem ----
    {
        const float4* src = (const float4*)(x + (size_t)b * NROWS * CDIM);
        #pragma unroll
        for (int k = 0; k < (NROWS*CDIM/4)/NTHREADS; k++) {
            int e4 = tid + k * NTHREADS;
            float4 v = src[e4];
            int e = e4 * 4;
            int r = e >> 10, c = e & (CDIM - 1);
            *(float4*)(xs + rbase(r) + c) = v;
        }
    }
    __syncthreads();

    // ---- squared norms: 32 rows x 16 lanes ----
    {
        int r = tid >> 4, l16 = tid & 15;
        const float4* row = (const float4*)(xs + rbase(r));
        float s = 0.f;
        #pragma unroll
        for (int k = 0; k < 16; k++) {
            float4 v = row[l16 + 16 * k];
            s += v.x * v.x + v.y * v.y + v.z * v.z + v.w * v.w;
        }
        #pragma unroll
        for (int o = 8; o; o >>= 1) s += __shfl_down_sync(FULLM, s, o, 16);
        if (l16 == 0) sqp[r] = s;
    }

    // ---- 32x32 Gram: 8 c-slices x (8x8 threads, 4x4 tiles), conflict-free ----
    {
        int tslice = tid >> 6;
        int t64 = tid & 63;
        int ty = t64 >> 3, tx = t64 & 7;
        const float4* rA0 = (const float4*)(xs + rbase(4 * ty + 0));
        const float4* rA1 = (const float4*)(xs + rbase(4 * ty + 1));
        const float4* rA2 = (const float4*)(xs + rbase(4 * ty + 2));
        const float4* rA3 = (const float4*)(xs + rbase(4 * ty + 3));
        const float4* rB0 = (const float4*)(xs + rbase(4 * tx + 0));
        const float4* rB1 = (const float4*)(xs + rbase(4 * tx + 1));
        const float4* rB2 = (const float4*)(xs + rbase(4 * tx + 2));
        const float4* rB3 = (const float4*)(xs + rbase(4 * tx + 3));
        float acc[4][4];
        #pragma unroll
        for (int i = 0; i < 4; i++)
            #pragma unroll
            for (int j = 0; j < 4; j++) acc[i][j] = 0.f;

        int c4beg = tslice * 32;
        #pragma unroll 2
        for (int c4 = c4beg; c4 < c4beg + 32; c4++) {
            float4 a0 = rA0[c4], a1 = rA1[c4], a2 = rA2[c4], a3 = rA3[c4];
            float4 b0 = rB0[c4], b1 = rB1[c4], b2 = rB2[c4], b3 = rB3[c4];
            #define GRAM_STEP(C) { \
                float A0=a0.C, A1=a1.C, A2=a2.C, A3=a3.C; \
                float B0=b0.C, B1=b1.C, B2=b2.C, B3=b3.C; \
                acc[0][0]+=A0*B0; acc[0][1]+=A0*B1; acc[0][2]+=A0*B2; acc[0][3]+=A0*B3; \
                acc[1][0]+=A1*B0; acc[1][1]+=A1*B1; acc[1][2]+=A1*B2; acc[1][3]+=A1*B3; \
                acc[2][0]+=A2*B0; acc[2][1]+=A2*B1; acc[2][2]+=A2*B2; acc[2][3]+=A2*B3; \
                acc[3][0]+=A3*B0; acc[3][1]+=A3*B1; acc[3][2]+=A3*B2; acc[3][3]+=A3*B3; }
            GRAM_STEP(x) GRAM_STEP(y) GRAM_STEP(z) GRAM_STEP(w)
            #undef GRAM_STEP
        }
        float* gs = gtmp + tslice * 1056;
        #pragma unroll
        for (int i = 0; i < 4; i++)
            #pragma unroll
            for (int j = 0; j < 4; j++)
                gs[(4 * ty + i) * 33 + (4 * tx + j)] = acc[i][j];
    }
    __syncthreads();
    // deterministic 8-way reduce + finalize
    for (int e = tid; e < 1024; e += NTHREADS) {
        int i = e >> 5, j = e & 31;
        int o = i * 33 + j;
        float d = gtmp[o];
        #pragma unroll
        for (int s = 1; s < 8; s++) d += gtmp[s * 1056 + o];
        d2p[i * 33 + j] = sqp[i] + sqp[j] - 2.f * d;
    }
    __syncthreads();

    // register-replicated logical->physical slot table: lane l holds L[l] (slots 0..32)
    int myL = lane;

    // ---- merge steps ----
    for (int n = NROWS; n >= 2; n--) {
        int a, bb;
        if (n > 2) {
            // (A) argmin stage 1: one upper-triangle pair per thread
            int Li = __shfl_sync(FULLM, myL, ti);
            int Lj = __shfl_sync(FULLM, myL, tj & 31);
            unsigned long long key = ~0ull;
            if (tj < n) {
                float v = fmaxf(d2p[Li * 33 + Lj], 0.f);
                key = (((unsigned long long)__float_as_uint(v)) << 32) | (unsigned)((ti << 8) | tj);
            }
            #pragma unroll
            for (int o = 16; o; o >>= 1)
                key = u64min(key, __shfl_xor_sync(FULLM, key, o));
            if (lane == 0) redS[w] = key;
            __syncthreads();                           // BAR1
            // stage 2: all warps reduce the 16 partials
            unsigned long long v2 = redS[lane & 15];
            #pragma unroll
            for (int o = 8; o; o >>= 1)
                v2 = u64min(v2, __shfl_xor_sync(FULLM, v2, o));
            a  = (int)((v2 >> 8) & 0xff);
            bb = (int)(v2 & 0xff);
        } else {
            a = 0; bb = 1;
        }

        // (B) perm update in registers, redundantly identical across warps
        int pa, pb, sm = 0;
        {
            int oldL = myL;
            int la0 = __shfl_sync(FULLM, oldL, 0);
            int la1 = __shfl_sync(FULLM, oldL, 1);
            pa = (a == 0) ? la0 : ((a == 1) ? la1 : __shfl_sync(FULLM, oldL, a));
            pb = (bb == 1) ? la1 : __shfl_sync(FULLM, oldL, bb);
            if (n > 2) {
                int p = lane + 1;
                int v = (p == bb) ? 1 : ((a >= 2 && p == a) ? 0 : p);
                int slv = __shfl_sync(FULLM, oldL, v & 31);
                bool actL = (lane >= 1 && lane <= n - 2);
                unsigned bit = (actL && slv < 32) ? (1u << slv) : 0u;
                unsigned mask = __reduce_or_sync(FULLM, bit);
                unsigned excl = mask;
                if (pa < 32) excl |= (1u << pa);
                if (pb < 32) excl |= (1u << pb);
                unsigned freeb = ~excl;
                sm = freeb ? (__ffs(freeb) - 1) : 32;
                if (lane == 0) myL = sm;
                else if (actL) myL = slv;
            }
        }

        // (C) conv1d k=3 SAME over rows pa,pb + bias + relu; float2 + shuffles.
        // sm is disjoint from pa/pb and survivors -> write is hazard-free, no barrier.
        const float* ra = xs + rbase(pa);
        const float* rb = xs + rbase(pb);
        const int c0 = 2 * tid;
        float2 Av = ((const float2*)ra)[tid];
        float2 Bv = ((const float2*)rb)[tid];
        float am1 = __shfl_up_sync(FULLM, Av.y, 1);
        float bm1 = __shfl_up_sync(FULLM, Bv.y, 1);
        float a2  = __shfl_down_sync(FULLM, Av.x, 1);
        float bv2 = __shfl_down_sync(FULLM, Bv.x, 1);
        if (lane == 0)  { am1 = (tid == 0) ? 0.f : ra[c0 - 1];
                          bm1 = (tid == 0) ? 0.f : rb[c0 - 1]; }
        if (lane == 31) { a2  = (tid == NTHREADS - 1) ? 0.f : ra[c0 + 2];
                          bv2 = (tid == NTHREADS - 1) ? 0.f : rb[c0 + 2]; }
        float m0 = bc + w00 * am1  + w01 * Av.x + w02 * Av.y + w10 * bm1  + w11 * Bv.x + w12 * Bv.y;
        float m1 = bc + w00 * Av.x + w01 * Av.y + w02 * a2   + w10 * Bv.x + w11 * Bv.y + w12 * bv2;
        m0 = fmaxf(m0, 0.f); m1 = fmaxf(m1, 0.f);

        if (n == 2) {
            float* ob = out + (size_t)b * CDIM;
            ((float2*)ob)[tid] = make_float2(m0, m1);
            break;
        }

        float* rm = xs + rbase(sm);
        ((float2*)rm)[tid] = make_float2(m0, m1);
        float sq = m0 * m0 + m1 * m1;
        #pragma unroll
        for (int o = 16; o; o >>= 1) sq += __shfl_down_sync(FULLM, sq, o);
        if (lane == 0) fredS[w] = sq;
        __syncthreads();                               // BAR-D: rm + fred visible

        // (D) sqm from fred (all warps); tid0 persists sqp[sm]
        float sqm;
        {
            float v = fredS[lane & 15];
            #pragma unroll
            for (int o = 8; o; o >>= 1) v += __shfl_xor_sync(FULLM, v, o);
            sqm = v;
        }
        if (tid == 0) sqp[sm] = sqm;

        // (E) distance updates: warp w handles logical targets w+1 and w+17
        {
            int l1 = w + 1, l2 = w + 17;
            bool v1 = (l1 <= n - 2);
            bool v2 = (l2 <= n - 2);
            int t1 = __shfl_sync(FULLM, myL, l1 & 31);
            int t2 = __shfl_sync(FULLM, myL, l2 & 31);
            const float4* rm4 = (const float4*)rm;
            float4 rmv[8];
            float s1 = 0.f, s2 = 0.f;
            if (v1 || v2) {
                #pragma unroll
                for (int k = 0; k < 8; k++) rmv[k] = rm4[lane + 32 * k];
            }
            if (v1) {
                const float4* rt = (const float4*)(xs + rbase(t1));
                #pragma unroll
                for (int k = 0; k < 8; k++) {
                    float4 v = rt[lane + 32 * k];
                    s1 += rmv[k].x * v.x + rmv[k].y * v.y + rmv[k].z * v.z + rmv[k].w * v.w;
                }
            }
            if (v2) {
                const float4* rt = (const float4*)(xs + rbase(t2));
                #pragma unroll
                for (int k = 0; k < 8; k++) {
                    float4 v = rt[lane + 32 * k];
                    s2 += rmv[k].x * v.x + rmv[k].y * v.y + rmv[k].z * v.z + rmv[k].w * v.w;
                }
            }
            #pragma unroll
            for (int o = 16; o; o >>= 1) {
                s1 += __shfl_xor_sync(FULLM, s1, o);
                s2 += __shfl_xor_sync(FULLM, s2, o);
            }
            if (lane == 0) {
                if (v1) {
                    float d2 = sqm + sqp[t1] - 2.f * s1;
                    d2p[sm * 33 + t1] = d2;
                    d2p[t1 * 33 + sm] = d2;
                }
                if (v2) {
                    float d2 = sqm + sqp[t2] - 2.f * s2;
                    d2p[sm * 33 + t2] = d2;
                    d2p[t2 * 33 + sm] = d2;
                }
            }
        }
        __syncthreads();                               // BAR-E: d2p ready for next argmin
    }
}

extern "C" void kernel_launch(void* const* d_in, const int* in_sizes, int n_in,
                              void* d_out, int out_size)
{
    const float* x  = (const float*)d_in[0];
    const float* cw = (const float*)d_in[1];
    const float* cb = (const float*)d_in[2];
    float* out = (float*)d_out;
    cudaFuncSetAttribute(agg_kernel, cudaFuncAttributeMaxDynamicSharedMemorySize, SMEM_BYTES);
    agg_kernel<<<BATCH, NTHREADS, SMEM_BYTES>>>(x, cw, cb, out);
}

// round 16
// speedup vs baseline: 1.7734x; 1.0847x over previous
#include <cuda_runtime.h>

#define BATCH    512
#define NROWS    32
#define CDIM     1024
#define RPITCH   1032
#define NTHREADS 512
#define FULLM    0xffffffffu

// staggered row base (floats): rows 4 apart differ by 16B mod 128B -> conflict-free Gram
static __device__ __forceinline__ int rbase(int r) { return r * RPITCH + ((r >> 2) << 2); }

#define XS_FLOATS   (32 * RPITCH + 32 + RPITCH)   /* 33 rows; = 34088, even */
#define D2P_FLOATS  1090                          /* 33*33 = 1089, padded EVEN for 8B alignment below */
#define GTMP_FLOATS (8 * 1056)
#define SQP_FLOATS  34
#define FRED_FLOATS 16
#define SMEM_FLOATS (XS_FLOATS + D2P_FLOATS + GTMP_FLOATS + SQP_FLOATS + FRED_FLOATS)
#define SMEM_BYTES  (SMEM_FLOATS * 4 + 16 * 8 + 2 * 16 * 8 + 32)

static __device__ __forceinline__ unsigned long long u64min(unsigned long long a, unsigned long long b) {
    return a < b ? a : b;
}

__global__ __launch_bounds__(NTHREADS, 1)
void agg_kernel(const float* __restrict__ x,
                const float* __restrict__ cw,
                const float* __restrict__ cb,
                float* __restrict__ out)
{
    extern __shared__ float smf[];
    float* xs    = smf;
    float* d2p   = smf + XS_FLOATS;
    float* gtmp  = d2p + D2P_FLOATS;
    float* sqp   = gtmp + GTMP_FLOATS;
    float* fredS = sqp + SQP_FLOATS;
    unsigned long long* redS = (unsigned long long*)(fredS + FRED_FLOATS);           // 16 u64
    unsigned long long (*redP)[16] = (unsigned long long (*)[16])(redS + 16);        // [2][16] u64

    const int tid  = threadIdx.x;
    const int w    = tid >> 5;
    const int lane = tid & 31;
    const int b    = blockIdx.x;

    const float w00 = cw[0], w01 = cw[1], w02 = cw[2];
    const float w10 = cw[3], w11 = cw[4], w12 = cw[5];
    const float bc  = cb[0];

    // static upper-triangle pair for this thread: tid -> (ti, tj), ti < tj < 32
    int ti = 0, tj = 0;
    {
        int k = tid, cnt = 31;
        if (tid < 496) {
            while (k >= cnt) { k -= cnt; ti++; cnt--; }
            tj = ti + 1 + k;
        } else { ti = 0; tj = 32; }   // tj=32 -> never valid
    }

    // ---- load batch rows into staggered smem ----
    {
        const float4* src = (const float4*)(x + (size_t)b * NROWS * CDIM);
        #pragma unroll
        for (int k = 0; k < (NROWS*CDIM/4)/NTHREADS; k++) {
            int e4 = tid + k * NTHREADS;
            float4 v = src[e4];
            int e = e4 * 4;
            int r = e >> 10, c = e & (CDIM - 1);
            *(float4*)(xs + rbase(r) + c) = v;
        }
    }
    __syncthreads();

    // ---- squared norms: 32 rows x 16 lanes ----
    {
        int r = tid >> 4, l16 = tid & 15;
        const float4* row = (const float4*)(xs + rbase(r));
        float s = 0.f;
        #pragma unroll
        for (int k = 0; k < 16; k++) {
            float4 v = row[l16 + 16 * k];
            s += v.x * v.x + v.y * v.y + v.z * v.z + v.w * v.w;
        }
        #pragma unroll
        for (int o = 8; o; o >>= 1) s += __shfl_down_sync(FULLM, s, o, 16);
        if (l16 == 0) sqp[r] = s;
    }

    // ---- 32x32 Gram: 8 c-slices x (8x8 threads, 4x4 tiles), conflict-free ----
    {
        int tslice = tid >> 6;
        int t64 = tid & 63;
        int ty = t64 >> 3, tx = t64 & 7;
        const float4* rA0 = (const float4*)(xs + rbase(4 * ty + 0));
        const float4* rA1 = (const float4*)(xs + rbase(4 * ty + 1));
        const float4* rA2 = (const float4*)(xs + rbase(4 * ty + 2));
        const float4* rA3 = (const float4*)(xs + rbase(4 * ty + 3));
        const float4* rB0 = (const float4*)(xs + rbase(4 * tx + 0));
        const float4* rB1 = (const float4*)(xs + rbase(4 * tx + 1));
        const float4* rB2 = (const float4*)(xs + rbase(4 * tx + 2));
        const float4* rB3 = (const float4*)(xs + rbase(4 * tx + 3));
        float acc[4][4];
        #pragma unroll
        for (int i = 0; i < 4; i++)
            #pragma unroll
            for (int j = 0; j < 4; j++) acc[i][j] = 0.f;

        int c4beg = tslice * 32;
        #pragma unroll 2
        for (int c4 = c4beg; c4 < c4beg + 32; c4++) {
            float4 a0 = rA0[c4], a1 = rA1[c4], a2 = rA2[c4], a3 = rA3[c4];
            float4 b0 = rB0[c4], b1 = rB1[c4], b2 = rB2[c4], b3 = rB3[c4];
            #define GRAM_STEP(C) { \
                float A0=a0.C, A1=a1.C, A2=a2.C, A3=a3.C; \
                float B0=b0.C, B1=b1.C, B2=b2.C, B3=b3.C; \
                acc[0][0]+=A0*B0; acc[0][1]+=A0*B1; acc[0][2]+=A0*B2; acc[0][3]+=A0*B3; \
                acc[1][0]+=A1*B0; acc[1][1]+=A1*B1; acc[1][2]+=A1*B2; acc[1][3]+=A1*B3; \
                acc[2][0]+=A2*B0; acc[2][1]+=A2*B1; acc[2][2]+=A2*B2; acc[2][3]+=A2*B3; \
                acc[3][0]+=A3*B0; acc[3][1]+=A3*B1; acc[3][2]+=A3*B2; acc[3][3]+=A3*B3; }
            GRAM_STEP(x) GRAM_STEP(y) GRAM_STEP(z) GRAM_STEP(w)
            #undef GRAM_STEP
        }
        float* gs = gtmp + tslice * 1056;
        #pragma unroll
        for (int i = 0; i < 4; i++)
            #pragma unroll
            for (int j = 0; j < 4; j++)
                gs[(4 * ty + i) * 33 + (4 * tx + j)] = acc[i][j];
    }
    __syncthreads();
    // deterministic 8-way reduce + finalize
    for (int e = tid; e < 1024; e += NTHREADS) {
        int i = e >> 5, j = e & 31;
        int o = i * 33 + j;
        float d = gtmp[o];
        #pragma unroll
        for (int s = 1; s < 8; s++) d += gtmp[s * 1056 + o];
        d2p[i * 33 + j] = sqp[i] + sqp[j] - 2.f * d;
    }
    __syncthreads();

    // register-replicated logical->physical slot table: lane l holds L[l] (slots 0..32)
    int myL = lane;

    // ---- initial full argmin for n=32 (identity L) ----
    int a, bb;
    {
        unsigned vb = 0xffffffffu, ib = 0xffffffffu;
        if (tj < 32) {
            float v = fmaxf(d2p[ti * 33 + tj], 0.f);
            vb = __float_as_uint(v);
            ib = (unsigned)((ti << 8) | tj);
        }
        unsigned vmin = __reduce_min_sync(FULLM, vb);
        unsigned imin = __reduce_min_sync(FULLM, (vb == vmin) ? ib : 0xffffffffu);
        if (lane == 0) redS[w] = (((unsigned long long)vmin) << 32) | imin;
        __syncthreads();
        unsigned long long kk = (lane < 16) ? redS[lane] : ~0ull;
        unsigned hi = (unsigned)(kk >> 32);
        unsigned hmin = __reduce_min_sync(FULLM, hi);
        unsigned lo = (hi == hmin) ? (unsigned)kk : 0xffffffffu;
        unsigned lmin = __reduce_min_sync(FULLM, lo);
        a  = (int)((lmin >> 8) & 0xff);
        bb = (int)(lmin & 0xff);
        __syncthreads();   // redS free for reuse by step loop
    }

    // ---- merge steps (argmin for step n computed during step n+1) ----
    for (int n = NROWS; n >= 2; n--) {
        const int np  = n - 1;       // rows after this merge
        const int buf = n & 1;

        // (B) perm update in registers, redundantly identical across warps
        int pa, pb, sm = 0;
        {
            int oldL = myL;
            int la0 = __shfl_sync(FULLM, oldL, 0);
            int la1 = __shfl_sync(FULLM, oldL, 1);
            pa = (a == 0) ? la0 : ((a == 1) ? la1 : __shfl_sync(FULLM, oldL, a));
            pb = (bb == 1) ? la1 : __shfl_sync(FULLM, oldL, bb);
            if (n > 2) {
                int p = lane + 1;
                int v = (p == bb) ? 1 : ((a >= 2 && p == a) ? 0 : p);
                int slv = __shfl_sync(FULLM, oldL, v & 31);
                bool actL = (lane >= 1 && lane <= n - 2);
                unsigned bit = (actL && slv < 32) ? (1u << slv) : 0u;
                unsigned mask = __reduce_or_sync(FULLM, bit);
                unsigned excl = mask;
                if (pa < 32) excl |= (1u << pa);
                if (pb < 32) excl |= (1u << pb);
                unsigned freeb = ~excl;
                sm = freeb ? (__ffs(freeb) - 1) : 32;
                if (lane == 0) myL = sm;
                else if (actL) myL = slv;
            }
        }

        // (A') early partial argmin for NEXT step over pairs with ti>=1
        // (d2p entries for survivor x survivor pairs are unchanged this step)
        if (np > 2) {
            int Li = __shfl_sync(FULLM, myL, ti);
            int Lj = __shfl_sync(FULLM, myL, tj & 31);
            unsigned vb = 0xffffffffu, ib = 0xffffffffu;
            if (ti >= 1 && tj <= np - 1) {
                float v = fmaxf(d2p[Li * 33 + Lj], 0.f);
                vb = __float_as_uint(v);
                ib = (unsigned)((ti << 8) | tj);
            }
            unsigned vmin = __reduce_min_sync(FULLM, vb);
            unsigned imin = __reduce_min_sync(FULLM, (vb == vmin) ? ib : 0xffffffffu);
            if (lane == 0) redP[buf][w] = (((unsigned long long)vmin) << 32) | imin;
        }

        // (C) conv1d k=3 SAME over rows pa,pb + bias + relu; float2 + shuffles.
        // sm is disjoint from pa/pb and survivors -> write is hazard-free, no barrier.
        const float* ra = xs + rbase(pa);
        const float* rb = xs + rbase(pb);
        const int c0 = 2 * tid;
        float2 Av = ((const float2*)ra)[tid];
        float2 Bv = ((const float2*)rb)[tid];
        float am1 = __shfl_up_sync(FULLM, Av.y, 1);
        float bm1 = __shfl_up_sync(FULLM, Bv.y, 1);
        float a2  = __shfl_down_sync(FULLM, Av.x, 1);
        float bv2 = __shfl_down_sync(FULLM, Bv.x, 1);
        if (lane == 0)  { am1 = (tid == 0) ? 0.f : ra[c0 - 1];
                          bm1 = (tid == 0) ? 0.f : rb[c0 - 1]; }
        if (lane == 31) { a2  = (tid == NTHREADS - 1) ? 0.f : ra[c0 + 2];
                          bv2 = (tid == NTHREADS - 1) ? 0.f : rb[c0 + 2]; }
        float m0 = bc + w00 * am1  + w01 * Av.x + w02 * Av.y + w10 * bm1  + w11 * Bv.x + w12 * Bv.y;
        float m1 = bc + w00 * Av.x + w01 * Av.y + w02 * a2   + w10 * Bv.x + w11 * Bv.y + w12 * bv2;
        m0 = fmaxf(m0, 0.f); m1 = fmaxf(m1, 0.f);

        if (n == 2) {
            float* ob = out + (size_t)b * CDIM;
            ((float2*)ob)[tid] = make_float2(m0, m1);
            break;
        }

        float* rm = xs + rbase(sm);
        ((float2*)rm)[tid] = make_float2(m0, m1);
        float sq = m0 * m0 + m1 * m1;
        #pragma unroll
        for (int o = 16; o; o >>= 1) sq += __shfl_down_sync(FULLM, sq, o);
        if (lane == 0) fredS[w] = sq;
        __syncthreads();                               // BAR-D: rm + fred visible

        // (D) sqm from fred (all warps); tid0 persists sqp[sm]
        float sqm;
        {
            float v = fredS[lane & 15];
            #pragma unroll
            for (int o = 8; o; o >>= 1) v += __shfl_xor_sync(FULLM, v, o);
            sqm = v;
        }
        if (tid == 0) sqp[sm] = sqm;

        // (E) distance updates: warp w handles logical targets w+1 and w+17;
        // lane 0 also emits the per-warp argmin key for the NEW-row distances.
        {
            int l1 = w + 1, l2 = w + 17;
            bool v1 = (l1 <= np - 1);
            bool v2 = (l2 <= np - 1);
            int t1 = __shfl_sync(FULLM, myL, l1 & 31);
            int t2 = __shfl_sync(FULLM, myL, l2 & 31);
            const float4* rm4 = (const float4*)rm;
            float4 rmv[8];
            float s1 = 0.f, s2 = 0.f;
            if (v1 || v2) {
                #pragma unroll
                for (int k = 0; k < 8; k++) rmv[k] = rm4[lane + 32 * k];
            }
            if (v1) {
                const float4* rt = (const float4*)(xs + rbase(t1));
                #pragma unroll
                for (int k = 0; k < 8; k++) {
                    float4 v = rt[lane + 32 * k];
                    s1 += rmv[k].x * v.x + rmv[k].y * v.y + rmv[k].z * v.z + rmv[k].w * v.w;
                }
            }
            if (v2) {
                const float4* rt = (const float4*)(xs + rbase(t2));
                #pragma unroll
                for (int k = 0; k < 8; k++) {
                    float4 v = rt[lane + 32 * k];
                    s2 += rmv[k].x * v.x + rmv[k].y * v.y + rmv[k].z * v.z + rmv[k].w * v.w;
                }
            }
            #pragma unroll
            for (int o = 16; o; o >>= 1) {
                s1 += __shfl_xor_sync(FULLM, s1, o);
                s2 += __shfl_xor_sync(FULLM, s2, o);
            }
            if (lane == 0) {
                unsigned long long key = ~0ull;
                if (v1) {
                    float d2 = sqm + sqp[t1] - 2.f * s1;
                    d2p[sm * 33 + t1] = d2;
                    d2p[t1 * 33 + sm] = d2;
                    float dv = fmaxf(d2, 0.f);
                    key = (((unsigned long long)__float_as_uint(dv)) << 32) | (unsigned)l1;
                }
                if (v2) {
                    float d2 = sqm + sqp[t2] - 2.f * s2;
                    d2p[sm * 33 + t2] = d2;
                    d2p[t2 * 33 + sm] = d2;
                    float dv = fmaxf(d2, 0.f);
                    key = u64min(key, (((unsigned long long)__float_as_uint(dv)) << 32) | (unsigned)l2);
                }
                redS[w] = key;
            }
        }
        __syncthreads();                               // BAR-E: d2p + redS ready

        // (F) combine: next step's argmin = min(partial pairs, new-row pairs)
        if (np > 2) {
            unsigned long long kk = (lane < 16) ? redP[buf][lane] : redS[lane - 16];
            unsigned hi = (unsigned)(kk >> 32);
            unsigned hmin = __reduce_min_sync(FULLM, hi);
            unsigned lo = (hi == hmin) ? (unsigned)kk : 0xffffffffu;
            unsigned lmin = __reduce_min_sync(FULLM, lo);
            a  = (int)((lmin >> 8) & 0xff);
            bb = (int)(lmin & 0xff);
        } else {
            a = 0; bb = 1;
        }
    }
}

extern "C" void kernel_launch(void* const* d_in, const int* in_sizes, int n_in,
                              void* d_out, int out_size)
{
    const float* x  = (const float*)d_in[0];
    const float* cw = (const float*)d_in[1];
    const float* cb = (const float*)d_in[2];
    float* out = (float*)d_out;
    cudaFuncSetAttribute(agg_kernel, cudaFuncAttributeMaxDynamicSharedMemorySize, SMEM_BYTES);
    agg_kernel<<<BATCH, NTHREADS, SMEM_BYTES>>>(x, cw, cb, out);
}